// round 4
// baseline (speedup 1.0000x reference)
#include <cuda_runtime.h>
#include <cstdint>

// ---------------------------------------------------------------------------
// RSSM rollout: H=16 steps, B=2048  (see R1 notes)
// R2: FFMA2 (fma.rn.f32x2) GEMMs with dup-A smem layout, double-buffered
//     smem + global prefetch, rebalanced grids.
// ---------------------------------------------------------------------------

#define B_       2048
#define DETER_   512
#define SC_      1024
#define ACT_     10
#define H_       16
#define KCAT     1552
#define OUTW     1536

__device__ float g_Wcat[2048 * KCAT];
__device__ float g_xh[B_ * KCAT];
__device__ float g_deter[B_ * DETER_];
__device__ float g_rz[B_ * 1024];
__device__ float g_xn[B_ * DETER_];
__device__ float g_hn[B_ * DETER_];
__device__ float g_h1raw[B_ * DETER_];
__device__ float g_h1[B_ * DETER_];
__device__ float g_logits[B_ * SC_];

// ---------------------------------------------------------------------------
// Threefry-2x32 (JAX schedule)
// ---------------------------------------------------------------------------
__host__ __device__ __forceinline__ uint32_t rotl32(uint32_t v, int d) {
    return (v << d) | (v >> (32 - d));
}
__host__ __device__ __forceinline__ void threefry2x32(uint32_t k0, uint32_t k1,
                                                      uint32_t x0, uint32_t x1,
                                                      uint32_t& o0, uint32_t& o1) {
    uint32_t ks0 = k0, ks1 = k1, ks2 = k0 ^ k1 ^ 0x1BD11BDAu;
    x0 += ks0; x1 += ks1;
    x0 += x1; x1 = rotl32(x1, 13); x1 ^= x0;
    x0 += x1; x1 = rotl32(x1, 15); x1 ^= x0;
    x0 += x1; x1 = rotl32(x1, 26); x1 ^= x0;
    x0 += x1; x1 = rotl32(x1, 6);  x1 ^= x0;
    x0 += ks1; x1 += ks2 + 1u;
    x0 += x1; x1 = rotl32(x1, 17); x1 ^= x0;
    x0 += x1; x1 = rotl32(x1, 29); x1 ^= x0;
    x0 += x1; x1 = rotl32(x1, 16); x1 ^= x0;
    x0 += x1; x1 = rotl32(x1, 24); x1 ^= x0;
    x0 += ks2; x1 += ks0 + 2u;
    x0 += x1; x1 = rotl32(x1, 13); x1 ^= x0;
    x0 += x1; x1 = rotl32(x1, 15); x1 ^= x0;
    x0 += x1; x1 = rotl32(x1, 26); x1 ^= x0;
    x0 += x1; x1 = rotl32(x1, 6);  x1 ^= x0;
    x0 += ks0; x1 += ks1 + 3u;
    x0 += x1; x1 = rotl32(x1, 17); x1 ^= x0;
    x0 += x1; x1 = rotl32(x1, 29); x1 ^= x0;
    x0 += x1; x1 = rotl32(x1, 16); x1 ^= x0;
    x0 += x1; x1 = rotl32(x1, 24); x1 ^= x0;
    x0 += ks1; x1 += ks2 + 4u;
    x0 += x1; x1 = rotl32(x1, 13); x1 ^= x0;
    x0 += x1; x1 = rotl32(x1, 15); x1 ^= x0;
    x0 += x1; x1 = rotl32(x1, 26); x1 ^= x0;
    x0 += x1; x1 = rotl32(x1, 6);  x1 ^= x0;
    x0 += ks2; x1 += ks0 + 5u;
    o0 = x0; o1 = x1;
}

// ---------------------------------------------------------------------------
// Init / weight prep (one-time)
// ---------------------------------------------------------------------------
__global__ void init_kernel(const float* __restrict__ stoch0,
                            const float* __restrict__ act_seq,
                            const float* __restrict__ deter0) {
    int gid = blockIdx.x * blockDim.x + threadIdx.x;
    if (gid >= B_ * KCAT) return;
    int b = gid / KCAT, k = gid % KCAT;
    float v = 0.f;
    if (k < SC_)             v = stoch0[b * SC_ + k];
    else if (k < SC_ + ACT_) v = act_seq[b * ACT_ + (k - SC_)];
    else if (k < 1546)       v = deter0[b * DETER_ + (k - SC_ - ACT_)];
    g_xh[gid] = v;
    if (k < DETER_) g_deter[b * DETER_ + k] = deter0[b * DETER_ + k];
}

__global__ void wprep_kernel(const float* __restrict__ W_ih,
                             const float* __restrict__ W_hh) {
    int gid = blockIdx.x * blockDim.x + threadIdx.x;
    if (gid >= 2048 * KCAT) return;
    int r = gid / KCAT, k = gid % KCAT;
    float v = 0.f;
    if (r < 1024) {
        if (k < 1034)       v = W_ih[r * 1034 + k];
        else if (k < 1546)  v = W_hh[r * 512 + (k - 1034)];
    } else if (r < 1536) {
        if (k < 1034)       v = W_ih[r * 1034 + k];
    } else {
        if (k >= 1034 && k < 1546) v = W_hh[(r - 512) * 512 + (k - 1034)];
    }
    g_Wcat[gid] = v;
}

// ---------------------------------------------------------------------------
// FFMA2 GEMM core: C[m,n] = sum_k A[m,k]*W[n,k]
// Block tile BM x 128, 256 threads, per-thread (BM/16) x 8 accumulators held
// as f32x2 pairs. A is stored duplicated in smem: (a,a) pairs -> direct FFMA2
// broadcast operand. Double-buffered smem, one __syncthreads per k-step(8).
// ---------------------------------------------------------------------------
__device__ __forceinline__ void ffma2(unsigned long long& acc,
                                      unsigned long long a,
                                      unsigned long long b) {
    asm("fma.rn.f32x2 %0, %1, %2, %0;" : "+l"(acc) : "l"(a), "l"(b));
}

template <int BM>
__device__ __forceinline__ void gemm_f32x2(
    const float* __restrict__ A, int lda,
    const float* __restrict__ W, int ldw,
    int klo, int khi, int bm, int bn,
    unsigned long long (&acc)[BM / 16][4],
    float* sA, float* sB) {
    constexpr int R = BM / 16;
    constexpr int SA_STR = 8 * 2 * BM;   // floats per buffer
    constexpr int SB_STR = 8 * 128;
    const int tid  = threadIdx.x;
    const int tx   = tid & 15;
    const int ty   = tid >> 4;
    const int la   = tid >> 1;           // 0..127
    const int lcol = (tid & 1) << 2;
    const bool doA = (la < BM);
    const float* Ap = A + (size_t)(bm + (doA ? la : 0)) * lda + lcol;
    const float* Wp = W + (size_t)(bn + la) * ldw + lcol;

    const int nk = (khi - klo) >> 3;

    float4 av = doA ? *(const float4*)(Ap + klo) : make_float4(0, 0, 0, 0);
    float4 wv = *(const float4*)(Wp + klo);

    // store slab into buffer `buf`
    auto store_slab = [&](int buf, const float4& a4, const float4& w4) {
        float* sa = sA + buf * SA_STR;
        float* sb = sB + buf * SB_STR;
        if (doA) {
#pragma unroll
            for (int c = 0; c < 4; c++) {
                float v = (&a4.x)[c];
                *(float2*)&sa[(lcol + c) * (2 * BM) + 2 * la] = make_float2(v, v);
            }
        }
#pragma unroll
        for (int c = 0; c < 4; c++)
            sb[(lcol + c) * 128 + la] = (&w4.x)[c];
    };

    auto compute = [&](int buf) {
        const float* sa = sA + buf * SA_STR;
        const float* sb = sB + buf * SB_STR;
#pragma unroll
        for (int kk = 0; kk < 8; kk++) {
            unsigned long long a2[R], b2[4];
            const ulonglong2* ap =
                (const ulonglong2*)(sa + kk * (2 * BM) + ty * (2 * R));
#pragma unroll
            for (int r = 0; r < R / 2; r++) {
                ulonglong2 t = ap[r];
                a2[2 * r] = t.x;
                a2[2 * r + 1] = t.y;
            }
            const ulonglong2* bp = (const ulonglong2*)(sb + kk * 128 + tx * 8);
            ulonglong2 t0 = bp[0], t1 = bp[1];
            b2[0] = t0.x; b2[1] = t0.y; b2[2] = t1.x; b2[3] = t1.y;
#pragma unroll
            for (int r = 0; r < R; r++)
#pragma unroll
                for (int j = 0; j < 4; j++)
                    ffma2(acc[r][j], a2[r], b2[j]);
        }
    };

    store_slab(0, av, wv);
    __syncthreads();
    int cur = 0;
    for (int it = 1; it < nk; it++) {
        int k0 = klo + it * 8;
        float4 av2 = doA ? *(const float4*)(Ap + k0) : make_float4(0, 0, 0, 0);
        float4 wv2 = *(const float4*)(Wp + k0);
        compute(cur);
        store_slab(cur ^ 1, av2, wv2);
        __syncthreads();
        cur ^= 1;
    }
    compute(cur);
}

__device__ __forceinline__ void unpack8(const unsigned long long p[4], float f[8]) {
#pragma unroll
    for (int j = 0; j < 4; j++) {
        f[2 * j]     = __uint_as_float((uint32_t)p[j]);
        f[2 * j + 1] = __uint_as_float((uint32_t)(p[j] >> 32));
    }
}

// ---------------------------------------------------------------------------
// GRU GEMM: virtual N=2048 [rz | xn | hn], BM=64 tiles for balance
// ---------------------------------------------------------------------------
__global__ void __launch_bounds__(256) gru_gemm2(const float* __restrict__ b_ih,
                                                 const float* __restrict__ b_hh) {
    __shared__ float sA[2 * 8 * 128];   // BM=64 -> 2*8*2*64
    __shared__ float sB[2 * 8 * 128];
    unsigned long long acc[4][4] = {};
    int bm = blockIdx.y * 64, bn = blockIdx.x * 128;
    int klo, khi;
    if (bn < 1024)      { klo = 0;    khi = KCAT; }
    else if (bn < 1536) { klo = 0;    khi = 1040; }
    else                { klo = 1032; khi = KCAT; }
    gemm_f32x2<64>(g_xh, KCAT, g_Wcat, KCAT, klo, khi, bm, bn, acc, sA, sB);
    int tx = threadIdx.x & 15, ty = threadIdx.x >> 4;
#pragma unroll
    for (int r = 0; r < 4; r++) {
        int m = bm + ty * 4 + r;
        float f[8];
        unpack8(acc[r], f);
#pragma unroll
        for (int j = 0; j < 8; j++) {
            int n = bn + tx * 8 + j;
            float v = f[j];
            if (n < 1024)       g_rz[m * 1024 + n] = v + b_ih[n] + b_hh[n];
            else if (n < 1536)  g_xn[m * 512 + (n - 1024)] = v + b_ih[n];
            else                g_hn[m * 512 + (n - 1536)] = v + b_hh[(n - 1536) + 1024];
        }
    }
}

__global__ void __launch_bounds__(256) gemm_b1_2(const float* __restrict__ pW1,
                                                 const float* __restrict__ pb1) {
    __shared__ float sA[2 * 8 * 128];
    __shared__ float sB[2 * 8 * 128];
    unsigned long long acc[4][4] = {};
    int bm = blockIdx.y * 64, bn = blockIdx.x * 128;
    gemm_f32x2<64>(g_deter, 512, pW1, 512, 0, 512, bm, bn, acc, sA, sB);
    int tx = threadIdx.x & 15, ty = threadIdx.x >> 4;
#pragma unroll
    for (int r = 0; r < 4; r++) {
        int m = bm + ty * 4 + r;
        float f[8];
        unpack8(acc[r], f);
#pragma unroll
        for (int j = 0; j < 8; j++) {
            int n = bn + tx * 8 + j;
            g_h1raw[m * 512 + n] = f[j] + pb1[n];
        }
    }
}

__global__ void __launch_bounds__(256) gemm_c_2(const float* __restrict__ pW2,
                                                const float* __restrict__ pb2) {
    __shared__ float sA[2 * 8 * 256];   // BM=128
    __shared__ float sB[2 * 8 * 128];
    unsigned long long acc[8][4] = {};
    int bm = blockIdx.y * 128, bn = blockIdx.x * 128;
    gemm_f32x2<128>(g_h1, 512, pW2, 512, 0, 512, bm, bn, acc, sA, sB);
    int tx = threadIdx.x & 15, ty = threadIdx.x >> 4;
#pragma unroll
    for (int r = 0; r < 8; r++) {
        int m = bm + ty * 8 + r;
        float f[8];
        unpack8(acc[r], f);
#pragma unroll
        for (int j = 0; j < 8; j++) {
            int n = bn + tx * 8 + j;
            g_logits[m * 1024 + n] = f[j] + pb2[n];
        }
    }
}

// ---------------------------------------------------------------------------
// Elementwise kernels (unchanged from R1 — proven bit-correct)
// ---------------------------------------------------------------------------
__global__ void gates_kernel(float* __restrict__ out, int t) {
    int gid = blockIdx.x * blockDim.x + threadIdx.x;
    int b = gid >> 9, d = gid & 511;
    float sr = g_rz[b * 1024 + d];
    float sz = g_rz[b * 1024 + 512 + d];
    float xn = g_xn[b * 512 + d];
    float hn = g_hn[b * 512 + d];
    float h  = g_xh[b * KCAT + 1034 + d];
    float r = 1.f / (1.f + expf(-sr));
    float z = 1.f / (1.f + expf(-sz));
    float n = tanhf(xn + r * hn);
    float dn = (1.f - z) * n + z * h;
    g_xh[b * KCAT + 1034 + d] = dn;
    g_deter[b * 512 + d] = dn;
    out[((size_t)t * B_ + b) * OUTW + d] = dn;
}

__global__ void ln_kernel(const float* __restrict__ pg, const float* __restrict__ pbeta) {
    __shared__ float red[256];
    int b = blockIdx.x, tid = threadIdx.x;
    const float* x = g_h1raw + b * 512;
    float v0 = x[tid], v1 = x[tid + 256];
    red[tid] = v0 + v1;
    __syncthreads();
    for (int s = 128; s > 0; s >>= 1) {
        if (tid < s) red[tid] += red[tid + s];
        __syncthreads();
    }
    float mean = red[0] * (1.f / 512.f);
    __syncthreads();
    float d0 = v0 - mean, d1 = v1 - mean;
    red[tid] = d0 * d0 + d1 * d1;
    __syncthreads();
    for (int s = 128; s > 0; s >>= 1) {
        if (tid < s) red[tid] += red[tid + s];
        __syncthreads();
    }
    float var = red[0] * (1.f / 512.f);
    float rstd = rsqrtf(var + 1e-5f);
    float y0 = d0 * rstd * pg[tid] + pbeta[tid];
    float y1 = d1 * rstd * pg[tid + 256] + pbeta[tid + 256];
    g_h1[b * 512 + tid]       = y0 * (1.f / (1.f + expf(-y0)));
    g_h1[b * 512 + tid + 256] = y1 * (1.f / (1.f + expf(-y1)));
}

__global__ void sample_kernel(const float* __restrict__ act_seq,
                              float* __restrict__ out,
                              int t, uint32_t k0, uint32_t k1) {
    int gid = blockIdx.x * blockDim.x + threadIdx.x;
    int b = gid >> 5, s = gid & 31;
    const float* lg = g_logits + b * 1024 + s * 32;
    float best = -1e30f;
    int bi = 0;
#pragma unroll 4
    for (int c = 0; c < 32; c++) {
        uint32_t idx = (uint32_t)(b * 1024 + s * 32 + c);
        uint32_t o0, o1;
        threefry2x32(k0, k1, 0u, idx, o0, o1);
        uint32_t bits = o0 ^ o1;
        float u = __uint_as_float((bits >> 9) | 0x3f800000u) - 1.0f;
        u = fmaxf(u, 1.1754943508222875e-38f);
        float g = -logf(-logf(u));
        float v = g + lg[c];
        if (v > best) { best = v; bi = c; }
    }
    float* xs = g_xh + b * KCAT + s * 32;
    float* os = out + ((size_t)t * B_ + b) * OUTW + 512 + s * 32;
#pragma unroll
    for (int c = 0; c < 32; c++) {
        float v = (c == bi) ? 1.0f : 0.0f;
        xs[c] = v;
        os[c] = v;
    }
    if (t < H_ - 1 && s < ACT_) {
        g_xh[b * KCAT + SC_ + s] = act_seq[(((size_t)(t + 1)) * B_ + b) * ACT_ + s];
    }
}

// ---------------------------------------------------------------------------
// Host launcher
// ---------------------------------------------------------------------------
extern "C" void kernel_launch(void* const* d_in, const int* in_sizes, int n_in,
                              void* d_out, int out_size) {
    const float* act    = (const float*)d_in[0];
    const float* deter0 = (const float*)d_in[1];
    const float* stoch0 = (const float*)d_in[2];
    const float* W_ih   = (const float*)d_in[3];
    const float* b_ih   = (const float*)d_in[4];
    const float* W_hh   = (const float*)d_in[5];
    const float* b_hh   = (const float*)d_in[6];
    const float* pW1    = (const float*)d_in[7];
    const float* pb1    = (const float*)d_in[8];
    const float* pg     = (const float*)d_in[9];
    const float* pbeta  = (const float*)d_in[10];
    const float* pW2    = (const float*)d_in[11];
    const float* pb2    = (const float*)d_in[12];
    float* out = (float*)d_out;

    uint32_t keys[H_][2];
    for (int t = 0; t < H_; t++) {
        uint32_t o0, o1;
        threefry2x32(0u, 42u, 0u, (uint32_t)t, o0, o1);
        keys[t][0] = o0;
        keys[t][1] = o1;
    }

    cudaStream_t st = cudaStreamPerThread;
    int nfill = B_ * KCAT;
    init_kernel<<<(nfill + 255) / 256, 256, 0, st>>>(stoch0, act, deter0);
    wprep_kernel<<<(2048 * KCAT + 255) / 256, 256, 0, st>>>(W_ih, W_hh);

    for (int t = 0; t < H_; t++) {
        gru_gemm2<<<dim3(16, 32), 256, 0, st>>>(b_ih, b_hh);
        gates_kernel<<<(B_ * DETER_) / 256, 256, 0, st>>>(out, t);
        gemm_b1_2<<<dim3(4, 32), 256, 0, st>>>(pW1, pb1);
        ln_kernel<<<B_, 256, 0, st>>>(pg, pbeta);
        gemm_c_2<<<dim3(8, 16), 256, 0, st>>>(pW2, pb2);
        sample_kernel<<<(B_ * 32) / 128, 128, 0, st>>>(act, out, t, keys[t][0], keys[t][1]);
    }
}

// round 5
// speedup vs baseline: 1.1318x; 1.1318x over previous
#include <cuda_runtime.h>
#include <cstdint>

// ---------------------------------------------------------------------------
// RSSM rollout: H=16 steps, B=2048
// R4: R1's proven scalar-FFMA SGEMM core + register-prefetch double buffering
//     (single __syncthreads per k-slab), BM=64 tiles for GRU/b1 occupancy.
//     Accumulation order identical to R1 -> bit-identical output.
// ---------------------------------------------------------------------------

#define B_       2048
#define DETER_   512
#define SC_      1024
#define ACT_     10
#define H_       16
#define KCAT     1552
#define OUTW     1536

__device__ float g_Wcat[2048 * KCAT];
__device__ float g_xh[B_ * KCAT];
__device__ float g_deter[B_ * DETER_];
__device__ float g_rz[B_ * 1024];
__device__ float g_xn[B_ * DETER_];
__device__ float g_hn[B_ * DETER_];
__device__ float g_h1raw[B_ * DETER_];
__device__ float g_h1[B_ * DETER_];
__device__ float g_logits[B_ * SC_];

// ---------------------------------------------------------------------------
// Threefry-2x32 (JAX schedule) — proven bit-exact, do not touch
// ---------------------------------------------------------------------------
__host__ __device__ __forceinline__ uint32_t rotl32(uint32_t v, int d) {
    return (v << d) | (v >> (32 - d));
}
__host__ __device__ __forceinline__ void threefry2x32(uint32_t k0, uint32_t k1,
                                                      uint32_t x0, uint32_t x1,
                                                      uint32_t& o0, uint32_t& o1) {
    uint32_t ks0 = k0, ks1 = k1, ks2 = k0 ^ k1 ^ 0x1BD11BDAu;
    x0 += ks0; x1 += ks1;
    x0 += x1; x1 = rotl32(x1, 13); x1 ^= x0;
    x0 += x1; x1 = rotl32(x1, 15); x1 ^= x0;
    x0 += x1; x1 = rotl32(x1, 26); x1 ^= x0;
    x0 += x1; x1 = rotl32(x1, 6);  x1 ^= x0;
    x0 += ks1; x1 += ks2 + 1u;
    x0 += x1; x1 = rotl32(x1, 17); x1 ^= x0;
    x0 += x1; x1 = rotl32(x1, 29); x1 ^= x0;
    x0 += x1; x1 = rotl32(x1, 16); x1 ^= x0;
    x0 += x1; x1 = rotl32(x1, 24); x1 ^= x0;
    x0 += ks2; x1 += ks0 + 2u;
    x0 += x1; x1 = rotl32(x1, 13); x1 ^= x0;
    x0 += x1; x1 = rotl32(x1, 15); x1 ^= x0;
    x0 += x1; x1 = rotl32(x1, 26); x1 ^= x0;
    x0 += x1; x1 = rotl32(x1, 6);  x1 ^= x0;
    x0 += ks0; x1 += ks1 + 3u;
    x0 += x1; x1 = rotl32(x1, 17); x1 ^= x0;
    x0 += x1; x1 = rotl32(x1, 29); x1 ^= x0;
    x0 += x1; x1 = rotl32(x1, 16); x1 ^= x0;
    x0 += x1; x1 = rotl32(x1, 24); x1 ^= x0;
    x0 += ks1; x1 += ks2 + 4u;
    x0 += x1; x1 = rotl32(x1, 13); x1 ^= x0;
    x0 += x1; x1 = rotl32(x1, 15); x1 ^= x0;
    x0 += x1; x1 = rotl32(x1, 26); x1 ^= x0;
    x0 += x1; x1 = rotl32(x1, 6);  x1 ^= x0;
    x0 += ks2; x1 += ks0 + 5u;
    o0 = x0; o1 = x1;
}

// ---------------------------------------------------------------------------
// Init / weight prep (one-time)
// ---------------------------------------------------------------------------
__global__ void init_kernel(const float* __restrict__ stoch0,
                            const float* __restrict__ act_seq,
                            const float* __restrict__ deter0) {
    int gid = blockIdx.x * blockDim.x + threadIdx.x;
    if (gid >= B_ * KCAT) return;
    int b = gid / KCAT, k = gid % KCAT;
    float v = 0.f;
    if (k < SC_)             v = stoch0[b * SC_ + k];
    else if (k < SC_ + ACT_) v = act_seq[b * ACT_ + (k - SC_)];
    else if (k < 1546)       v = deter0[b * DETER_ + (k - SC_ - ACT_)];
    g_xh[gid] = v;
    if (k < DETER_) g_deter[b * DETER_ + k] = deter0[b * DETER_ + k];
}

__global__ void wprep_kernel(const float* __restrict__ W_ih,
                             const float* __restrict__ W_hh) {
    int gid = blockIdx.x * blockDim.x + threadIdx.x;
    if (gid >= 2048 * KCAT) return;
    int r = gid / KCAT, k = gid % KCAT;
    float v = 0.f;
    if (r < 1024) {
        if (k < 1034)       v = W_ih[r * 1034 + k];
        else if (k < 1546)  v = W_hh[r * 512 + (k - 1034)];
    } else if (r < 1536) {
        if (k < 1034)       v = W_ih[r * 1034 + k];
    } else {
        if (k >= 1034 && k < 1546) v = W_hh[(r - 512) * 512 + (k - 1034)];
    }
    g_Wcat[gid] = v;
}

// ---------------------------------------------------------------------------
// Scalar-FFMA GEMM core, double-buffered smem + register prefetch.
// Block tile BM x 128, 256 threads. Per-thread (BM/16) x 8 accumulators.
// C[m,n] = sum_k A[m,k] * W[n,k]. One __syncthreads per 8-wide k-slab.
// ---------------------------------------------------------------------------
template <int BM>
__device__ __forceinline__ void gemm_core2(
    const float* __restrict__ A, int lda,
    const float* __restrict__ W, int ldw,
    int klo, int khi, int bm, int bn,
    float (&acc)[BM / 16][8], float* sA, float* sB) {
    constexpr int R = BM / 16;
    constexpr int SA_STR = 8 * BM;
    constexpr int SB_STR = 8 * 128;
    const int tid  = threadIdx.x;
    const int tx   = tid & 15;
    const int ty   = tid >> 4;
    const int lrow = tid >> 1;             // 0..127
    const int lcol = (tid & 1) << 2;       // 0 or 4
    const bool doA = (lrow < BM);
    const float* Ap = A + (size_t)(bm + (doA ? lrow : 0)) * lda + lcol;
    const float* Wp = W + (size_t)(bn + lrow) * ldw + lcol;
    const int nk = (khi - klo) >> 3;

    auto store_slab = [&](int buf, const float4& a4, const float4& w4) {
        float* sa = sA + buf * SA_STR;
        float* sb = sB + buf * SB_STR;
        if (doA) {
            sa[(lcol + 0) * BM + lrow] = a4.x;
            sa[(lcol + 1) * BM + lrow] = a4.y;
            sa[(lcol + 2) * BM + lrow] = a4.z;
            sa[(lcol + 3) * BM + lrow] = a4.w;
        }
        sb[(lcol + 0) * 128 + lrow] = w4.x;
        sb[(lcol + 1) * 128 + lrow] = w4.y;
        sb[(lcol + 2) * 128 + lrow] = w4.z;
        sb[(lcol + 3) * 128 + lrow] = w4.w;
    };

    auto compute = [&](int buf) {
        const float* sa = sA + buf * SA_STR;
        const float* sb = sB + buf * SB_STR;
#pragma unroll
        for (int kk = 0; kk < 8; kk++) {
            float a[R], b[8];
#pragma unroll
            for (int r4 = 0; r4 < R / 4; r4++)
                *(float4*)(a + 4 * r4) =
                    *(const float4*)(sa + kk * BM + ty * R + 4 * r4);
            *(float4*)(b)     = *(const float4*)(sb + kk * 128 + tx * 8);
            *(float4*)(b + 4) = *(const float4*)(sb + kk * 128 + tx * 8 + 4);
#pragma unroll
            for (int i = 0; i < R; i++)
#pragma unroll
                for (int j = 0; j < 8; j++)
                    acc[i][j] += a[i] * b[j];
        }
    };

    float4 av = doA ? *(const float4*)(Ap + klo) : make_float4(0, 0, 0, 0);
    float4 wv = *(const float4*)(Wp + klo);
    store_slab(0, av, wv);
    __syncthreads();

    int cur = 0;
    for (int it = 1; it < nk; it++) {
        const int k0 = klo + it * 8;
        float4 av2 = doA ? *(const float4*)(Ap + k0) : make_float4(0, 0, 0, 0);
        float4 wv2 = *(const float4*)(Wp + k0);
        compute(cur);
        store_slab(cur ^ 1, av2, wv2);
        __syncthreads();
        cur ^= 1;
    }
    compute(cur);
}

// ---------------------------------------------------------------------------
// GRU GEMM: virtual N=2048 [rz(1024) | xn(512) | hn(512)], BM=64 tiles
// ---------------------------------------------------------------------------
__global__ void __launch_bounds__(256) gru_gemm2(const float* __restrict__ b_ih,
                                                 const float* __restrict__ b_hh) {
    __shared__ float sA[2 * 8 * 64];
    __shared__ float sB[2 * 8 * 128];
    float acc[4][8] = {};
    int bm = blockIdx.y * 64, bn = blockIdx.x * 128;
    int klo, khi;
    if (bn < 1024)      { klo = 0;    khi = KCAT; }
    else if (bn < 1536) { klo = 0;    khi = 1040; }
    else                { klo = 1032; khi = KCAT; }
    gemm_core2<64>(g_xh, KCAT, g_Wcat, KCAT, klo, khi, bm, bn, acc, sA, sB);
    int tx = threadIdx.x & 15, ty = threadIdx.x >> 4;
#pragma unroll
    for (int i = 0; i < 4; i++) {
        int m = bm + ty * 4 + i;
#pragma unroll
        for (int j = 0; j < 8; j++) {
            int n = bn + tx * 8 + j;
            float v = acc[i][j];
            if (n < 1024)       g_rz[m * 1024 + n] = v + b_ih[n] + b_hh[n];
            else if (n < 1536)  g_xn[m * 512 + (n - 1024)] = v + b_ih[n];
            else                g_hn[m * 512 + (n - 1536)] = v + b_hh[(n - 1536) + 1024];
        }
    }
}

__global__ void __launch_bounds__(256) gemm_b1_2(const float* __restrict__ pW1,
                                                 const float* __restrict__ pb1) {
    __shared__ float sA[2 * 8 * 64];
    __shared__ float sB[2 * 8 * 128];
    float acc[4][8] = {};
    int bm = blockIdx.y * 64, bn = blockIdx.x * 128;
    gemm_core2<64>(g_deter, 512, pW1, 512, 0, 512, bm, bn, acc, sA, sB);
    int tx = threadIdx.x & 15, ty = threadIdx.x >> 4;
#pragma unroll
    for (int i = 0; i < 4; i++) {
        int m = bm + ty * 4 + i;
#pragma unroll
        for (int j = 0; j < 8; j++) {
            int n = bn + tx * 8 + j;
            g_h1raw[m * 512 + n] = acc[i][j] + pb1[n];
        }
    }
}

__global__ void __launch_bounds__(256) gemm_c_2(const float* __restrict__ pW2,
                                                const float* __restrict__ pb2) {
    __shared__ float sA[2 * 8 * 128];
    __shared__ float sB[2 * 8 * 128];
    float acc[8][8] = {};
    int bm = blockIdx.y * 128, bn = blockIdx.x * 128;
    gemm_core2<128>(g_h1, 512, pW2, 512, 0, 512, bm, bn, acc, sA, sB);
    int tx = threadIdx.x & 15, ty = threadIdx.x >> 4;
#pragma unroll
    for (int i = 0; i < 8; i++) {
        int m = bm + ty * 8 + i;
#pragma unroll
        for (int j = 0; j < 8; j++) {
            int n = bn + tx * 8 + j;
            g_logits[m * 1024 + n] = acc[i][j] + pb2[n];
        }
    }
}

// ---------------------------------------------------------------------------
// Elementwise kernels (unchanged — proven bit-correct)
// ---------------------------------------------------------------------------
__global__ void gates_kernel(float* __restrict__ out, int t) {
    int gid = blockIdx.x * blockDim.x + threadIdx.x;
    int b = gid >> 9, d = gid & 511;
    float sr = g_rz[b * 1024 + d];
    float sz = g_rz[b * 1024 + 512 + d];
    float xn = g_xn[b * 512 + d];
    float hn = g_hn[b * 512 + d];
    float h  = g_xh[b * KCAT + 1034 + d];
    float r = 1.f / (1.f + expf(-sr));
    float z = 1.f / (1.f + expf(-sz));
    float n = tanhf(xn + r * hn);
    float dn = (1.f - z) * n + z * h;
    g_xh[b * KCAT + 1034 + d] = dn;
    g_deter[b * 512 + d] = dn;
    out[((size_t)t * B_ + b) * OUTW + d] = dn;
}

__global__ void ln_kernel(const float* __restrict__ pg, const float* __restrict__ pbeta) {
    __shared__ float red[256];
    int b = blockIdx.x, tid = threadIdx.x;
    const float* x = g_h1raw + b * 512;
    float v0 = x[tid], v1 = x[tid + 256];
    red[tid] = v0 + v1;
    __syncthreads();
    for (int s = 128; s > 0; s >>= 1) {
        if (tid < s) red[tid] += red[tid + s];
        __syncthreads();
    }
    float mean = red[0] * (1.f / 512.f);
    __syncthreads();
    float d0 = v0 - mean, d1 = v1 - mean;
    red[tid] = d0 * d0 + d1 * d1;
    __syncthreads();
    for (int s = 128; s > 0; s >>= 1) {
        if (tid < s) red[tid] += red[tid + s];
        __syncthreads();
    }
    float var = red[0] * (1.f / 512.f);
    float rstd = rsqrtf(var + 1e-5f);
    float y0 = d0 * rstd * pg[tid] + pbeta[tid];
    float y1 = d1 * rstd * pg[tid + 256] + pbeta[tid + 256];
    g_h1[b * 512 + tid]       = y0 * (1.f / (1.f + expf(-y0)));
    g_h1[b * 512 + tid + 256] = y1 * (1.f / (1.f + expf(-y1)));
}

__global__ void sample_kernel(const float* __restrict__ act_seq,
                              float* __restrict__ out,
                              int t, uint32_t k0, uint32_t k1) {
    int gid = blockIdx.x * blockDim.x + threadIdx.x;
    int b = gid >> 5, s = gid & 31;
    const float* lg = g_logits + b * 1024 + s * 32;
    float best = -1e30f;
    int bi = 0;
#pragma unroll 4
    for (int c = 0; c < 32; c++) {
        uint32_t idx = (uint32_t)(b * 1024 + s * 32 + c);
        uint32_t o0, o1;
        threefry2x32(k0, k1, 0u, idx, o0, o1);
        uint32_t bits = o0 ^ o1;
        float u = __uint_as_float((bits >> 9) | 0x3f800000u) - 1.0f;
        u = fmaxf(u, 1.1754943508222875e-38f);
        float g = -logf(-logf(u));
        float v = g + lg[c];
        if (v > best) { best = v; bi = c; }
    }
    float* xs = g_xh + b * KCAT + s * 32;
    float* os = out + ((size_t)t * B_ + b) * OUTW + 512 + s * 32;
#pragma unroll
    for (int c = 0; c < 32; c++) {
        float v = (c == bi) ? 1.0f : 0.0f;
        xs[c] = v;
        os[c] = v;
    }
    if (t < H_ - 1 && s < ACT_) {
        g_xh[b * KCAT + SC_ + s] = act_seq[(((size_t)(t + 1)) * B_ + b) * ACT_ + s];
    }
}

// ---------------------------------------------------------------------------
// Host launcher
// ---------------------------------------------------------------------------
extern "C" void kernel_launch(void* const* d_in, const int* in_sizes, int n_in,
                              void* d_out, int out_size) {
    const float* act    = (const float*)d_in[0];
    const float* deter0 = (const float*)d_in[1];
    const float* stoch0 = (const float*)d_in[2];
    const float* W_ih   = (const float*)d_in[3];
    const float* b_ih   = (const float*)d_in[4];
    const float* W_hh   = (const float*)d_in[5];
    const float* b_hh   = (const float*)d_in[6];
    const float* pW1    = (const float*)d_in[7];
    const float* pb1    = (const float*)d_in[8];
    const float* pg     = (const float*)d_in[9];
    const float* pbeta  = (const float*)d_in[10];
    const float* pW2    = (const float*)d_in[11];
    const float* pb2    = (const float*)d_in[12];
    float* out = (float*)d_out;

    uint32_t keys[H_][2];
    for (int t = 0; t < H_; t++) {
        uint32_t o0, o1;
        threefry2x32(0u, 42u, 0u, (uint32_t)t, o0, o1);
        keys[t][0] = o0;
        keys[t][1] = o1;
    }

    cudaStream_t st = cudaStreamPerThread;
    int nfill = B_ * KCAT;
    init_kernel<<<(nfill + 255) / 256, 256, 0, st>>>(stoch0, act, deter0);
    wprep_kernel<<<(2048 * KCAT + 255) / 256, 256, 0, st>>>(W_ih, W_hh);

    for (int t = 0; t < H_; t++) {
        gru_gemm2<<<dim3(16, 32), 256, 0, st>>>(b_ih, b_hh);
        gates_kernel<<<(B_ * DETER_) / 256, 256, 0, st>>>(out, t);
        gemm_b1_2<<<dim3(4, 32), 256, 0, st>>>(pW1, pb1);
        ln_kernel<<<B_, 256, 0, st>>>(pg, pbeta);
        gemm_c_2<<<dim3(8, 16), 256, 0, st>>>(pW2, pb2);
        sample_kernel<<<(B_ * 32) / 128, 128, 0, st>>>(act, out, t, keys[t][0], keys[t][1]);
    }
}

// round 7
// speedup vs baseline: 1.5268x; 1.3491x over previous
#include <cuda_runtime.h>
#include <cuda_bf16.h>
#include <cstdint>

// ---------------------------------------------------------------------------
// RSSM rollout: H=16 steps, B=2048
// R6: bf16x3 tensor-core GEMMs with RZ-bias-safe accumulation:
//     - a0b0 per-slab mma with C=0, flushed into RN fp32 register accumulator
//     - 5 correction products (<=2^-9) chained in separate TC accumulator
//     Error class == fp32 GEMM (matches R1, which passed at 6.4e-8).
// ---------------------------------------------------------------------------

#define B_       2048
#define DETER_   512
#define SC_      1024
#define ACT_     10
#define H_       16
#define KCAT     1552
#define OUTW     1536

#define KPAD     24                    // smem row stride (bf16), bank-conflict-free
#define PLANE_ELT (128 * KPAD)
#define SMEM_HALF (6 * PLANE_ELT)      // A(3 planes) + B(3 planes)
#define SMEM_BYTES (2 * SMEM_HALF * 2) // double-buffered = 73728 B

// fp32 state
__device__ float g_deter[B_ * DETER_];
__device__ float g_rz[B_ * 1024];
__device__ float g_xn[B_ * DETER_];
__device__ float g_hn[B_ * DETER_];
__device__ float g_h1raw[B_ * DETER_];
__device__ float g_logits[B_ * SC_];

// bf16x3 planes
__device__ __nv_bfloat16 gW0[2048 * KCAT], gW1[2048 * KCAT], gW2[2048 * KCAT];
__device__ __nv_bfloat16 gX0[B_ * KCAT],  gX1[B_ * KCAT],  gX2[B_ * KCAT];
__device__ __nv_bfloat16 gD0[B_ * DETER_], gD1[B_ * DETER_], gD2[B_ * DETER_];
__device__ __nv_bfloat16 gH0[B_ * DETER_], gH1[B_ * DETER_], gH2[B_ * DETER_];
__device__ __nv_bfloat16 gP10[512 * 512],  gP11[512 * 512],  gP12[512 * 512];
__device__ __nv_bfloat16 gP20[1024 * 512], gP21[1024 * 512], gP22[1024 * 512];

// ---------------------------------------------------------------------------
// Threefry-2x32 (JAX schedule) — proven bit-exact, do not touch
// ---------------------------------------------------------------------------
__host__ __device__ __forceinline__ uint32_t rotl32(uint32_t v, int d) {
    return (v << d) | (v >> (32 - d));
}
__host__ __device__ __forceinline__ void threefry2x32(uint32_t k0, uint32_t k1,
                                                      uint32_t x0, uint32_t x1,
                                                      uint32_t& o0, uint32_t& o1) {
    uint32_t ks0 = k0, ks1 = k1, ks2 = k0 ^ k1 ^ 0x1BD11BDAu;
    x0 += ks0; x1 += ks1;
    x0 += x1; x1 = rotl32(x1, 13); x1 ^= x0;
    x0 += x1; x1 = rotl32(x1, 15); x1 ^= x0;
    x0 += x1; x1 = rotl32(x1, 26); x1 ^= x0;
    x0 += x1; x1 = rotl32(x1, 6);  x1 ^= x0;
    x0 += ks1; x1 += ks2 + 1u;
    x0 += x1; x1 = rotl32(x1, 17); x1 ^= x0;
    x0 += x1; x1 = rotl32(x1, 29); x1 ^= x0;
    x0 += x1; x1 = rotl32(x1, 16); x1 ^= x0;
    x0 += x1; x1 = rotl32(x1, 24); x1 ^= x0;
    x0 += ks2; x1 += ks0 + 2u;
    x0 += x1; x1 = rotl32(x1, 13); x1 ^= x0;
    x0 += x1; x1 = rotl32(x1, 15); x1 ^= x0;
    x0 += x1; x1 = rotl32(x1, 26); x1 ^= x0;
    x0 += x1; x1 = rotl32(x1, 6);  x1 ^= x0;
    x0 += ks0; x1 += ks1 + 3u;
    x0 += x1; x1 = rotl32(x1, 17); x1 ^= x0;
    x0 += x1; x1 = rotl32(x1, 29); x1 ^= x0;
    x0 += x1; x1 = rotl32(x1, 16); x1 ^= x0;
    x0 += x1; x1 = rotl32(x1, 24); x1 ^= x0;
    x0 += ks1; x1 += ks2 + 4u;
    x0 += x1; x1 = rotl32(x1, 13); x1 ^= x0;
    x0 += x1; x1 = rotl32(x1, 15); x1 ^= x0;
    x0 += x1; x1 = rotl32(x1, 26); x1 ^= x0;
    x0 += x1; x1 = rotl32(x1, 6);  x1 ^= x0;
    x0 += ks2; x1 += ks0 + 5u;
    o0 = x0; o1 = x1;
}

// exact 3-way bf16 split: v = b0 + b1 + b2 + O(2^-27 v)
__device__ __forceinline__ void split3(float v, __nv_bfloat16& b0,
                                       __nv_bfloat16& b1, __nv_bfloat16& b2) {
    b0 = __float2bfloat16_rn(v);
    float r = v - __bfloat162float(b0);
    b1 = __float2bfloat16_rn(r);
    float r2 = r - __bfloat162float(b1);
    b2 = __float2bfloat16_rn(r2);
}

// ---------------------------------------------------------------------------
// Prep kernels (one-time)
// ---------------------------------------------------------------------------
__global__ void init_kernel(const float* __restrict__ stoch0,
                            const float* __restrict__ act_seq,
                            const float* __restrict__ deter0) {
    int gid = blockIdx.x * blockDim.x + threadIdx.x;
    if (gid >= B_ * KCAT) return;
    int b = gid / KCAT, k = gid % KCAT;
    float v = 0.f;
    if (k < SC_)             v = stoch0[b * SC_ + k];
    else if (k < SC_ + ACT_) v = act_seq[b * ACT_ + (k - SC_)];
    else if (k < 1546)       v = deter0[b * DETER_ + (k - SC_ - ACT_)];
    split3(v, gX0[gid], gX1[gid], gX2[gid]);
    if (k < DETER_) {
        float d = deter0[b * DETER_ + k];
        g_deter[b * DETER_ + k] = d;
        split3(d, gD0[b * DETER_ + k], gD1[b * DETER_ + k], gD2[b * DETER_ + k]);
    }
}

__global__ void wprep_kernel(const float* __restrict__ W_ih,
                             const float* __restrict__ W_hh) {
    int gid = blockIdx.x * blockDim.x + threadIdx.x;
    if (gid >= 2048 * KCAT) return;
    int r = gid / KCAT, k = gid % KCAT;
    float v = 0.f;
    if (r < 1024) {
        if (k < 1034)       v = W_ih[r * 1034 + k];
        else if (k < 1546)  v = W_hh[r * 512 + (k - 1034)];
    } else if (r < 1536) {
        if (k < 1034)       v = W_ih[r * 1034 + k];
    } else {
        if (k >= 1034 && k < 1546) v = W_hh[(r - 512) * 512 + (k - 1034)];
    }
    split3(v, gW0[gid], gW1[gid], gW2[gid]);
}

__global__ void pprep_kernel(const float* __restrict__ pW1,
                             const float* __restrict__ pW2) {
    int gid = blockIdx.x * blockDim.x + threadIdx.x;
    if (gid < 512 * 512) {
        split3(pW1[gid], gP10[gid], gP11[gid], gP12[gid]);
    } else if (gid < 512 * 512 + 1024 * 512) {
        int i = gid - 512 * 512;
        split3(pW2[i], gP20[i], gP21[i], gP22[i]);
    }
}

// ---------------------------------------------------------------------------
// MMA primitives
// ---------------------------------------------------------------------------
__device__ __forceinline__ void mma16816(float& c0, float& c1, float& c2, float& c3,
                                         uint32_t a0, uint32_t a1, uint32_t a2, uint32_t a3,
                                         uint32_t b0, uint32_t b1) {
    asm volatile(
        "mma.sync.aligned.m16n8k16.row.col.f32.bf16.bf16.f32 "
        "{%0,%1,%2,%3}, {%4,%5,%6,%7}, {%8,%9}, {%0,%1,%2,%3};"
        : "+f"(c0), "+f"(c1), "+f"(c2), "+f"(c3)
        : "r"(a0), "r"(a1), "r"(a2), "r"(a3), "r"(b0), "r"(b1));
}

__device__ __forceinline__ void ldm_x4(uint32_t& r0, uint32_t& r1,
                                       uint32_t& r2, uint32_t& r3, uint32_t addr) {
    asm volatile("ldmatrix.sync.aligned.m8n8.x4.shared.b16 {%0,%1,%2,%3}, [%4];"
                 : "=r"(r0), "=r"(r1), "=r"(r2), "=r"(r3) : "r"(addr));
}

// ---------------------------------------------------------------------------
// bf16x3 MMA core with RZ-safe accumulation.
// 128x128 block tile, 256 threads = 8 warps (2 m x 4 n), warp tile 64x32.
//   accM: fp32 register accumulators, fed per slab by pm = mma(a0,b0,C=0)
//   accC: TC-chained corrections (a2b0, a1b1, a0b2, a1b0, a0b1), |.| <= 2^-9
// ---------------------------------------------------------------------------
__device__ __forceinline__ void mma_core(
    const __nv_bfloat16* __restrict__ A0, const __nv_bfloat16* __restrict__ A1,
    const __nv_bfloat16* __restrict__ A2, int lda,
    const __nv_bfloat16* __restrict__ B0, const __nv_bfloat16* __restrict__ B1,
    const __nv_bfloat16* __restrict__ B2, int ldb,
    int klo, int khi, int bm, int bn,
    float (&accM)[4][4][4], float (&accC)[4][4][4]) {
    extern __shared__ __nv_bfloat16 sm[];
    const int tid = threadIdx.x;
    const int lane = tid & 31;
    const int wm = ((tid >> 5) >> 2) * 64;     // warp m offset: 0 or 64
    const int wn = ((tid >> 5) & 3) * 32;      // warp n offset: 0,32,64,96
    const int g = lane >> 2, tig = lane & 3;
    const int lrow = tid >> 1, lhalf = tid & 1;

    const __nv_bfloat16* Ap[3] = {
        A0 + (size_t)(bm + lrow) * lda + lhalf * 8,
        A1 + (size_t)(bm + lrow) * lda + lhalf * 8,
        A2 + (size_t)(bm + lrow) * lda + lhalf * 8};
    const __nv_bfloat16* Bp[3] = {
        B0 + (size_t)(bn + lrow) * ldb + lhalf * 8,
        B1 + (size_t)(bn + lrow) * ldb + lhalf * 8,
        B2 + (size_t)(bn + lrow) * ldb + lhalf * 8};

    const uint32_t smbase = (uint32_t)__cvta_generic_to_shared(sm);
    const int nk = (khi - klo) >> 4;
    const int st_off = lrow * KPAD + lhalf * 8;

    uint4 pa[3], pb[3];
    auto gload = [&](int k0) {
#pragma unroll
        for (int p = 0; p < 3; p++) {
            pa[p] = *(const uint4*)(Ap[p] + k0);
            pb[p] = *(const uint4*)(Bp[p] + k0);
        }
    };
    auto sstore = [&](int buf) {
        __nv_bfloat16* base = sm + buf * SMEM_HALF;
#pragma unroll
        for (int p = 0; p < 3; p++) {
            *(uint4*)(base + p * PLANE_ELT + st_off) = pa[p];
            *(uint4*)(base + (3 + p) * PLANE_ELT + st_off) = pb[p];
        }
    };
    auto compute = [&](int buf) {
        const uint32_t abase = smbase + (uint32_t)(buf * SMEM_HALF) * 2;
        const __nv_bfloat16* sbb = sm + buf * SMEM_HALF + 3 * PLANE_ELT;
#pragma unroll
        for (int mt = 0; mt < 4; mt++) {
            // A fragments, all 3 planes for this 16-row strip
            uint32_t a0f[4], a1f[4], a2f[4];
            uint32_t arow = (uint32_t)((wm + mt * 16 + (lane & 15)) * KPAD * 2) +
                            (uint32_t)((lane >> 4) * 16);
            ldm_x4(a0f[0], a0f[1], a0f[2], a0f[3], abase + 0 * PLANE_ELT * 2 + arow);
            ldm_x4(a1f[0], a1f[1], a1f[2], a1f[3], abase + 1 * PLANE_ELT * 2 + arow);
            ldm_x4(a2f[0], a2f[1], a2f[2], a2f[3], abase + 2 * PLANE_ELT * 2 + arow);
#pragma unroll
            for (int nt = 0; nt < 4; nt++) {
                const __nv_bfloat16* bq =
                    sbb + (wn + nt * 8 + g) * KPAD + 2 * tig;
                uint32_t b0lo = *(const uint32_t*)(bq);
                uint32_t b0hi = *(const uint32_t*)(bq + 8);
                uint32_t b1lo = *(const uint32_t*)(bq + PLANE_ELT);
                uint32_t b1hi = *(const uint32_t*)(bq + PLANE_ELT + 8);
                uint32_t b2lo = *(const uint32_t*)(bq + 2 * PLANE_ELT);
                uint32_t b2hi = *(const uint32_t*)(bq + 2 * PLANE_ELT + 8);
                // main product: fresh C=0, then RN FADD flush
                float p0 = 0.f, p1 = 0.f, p2 = 0.f, p3 = 0.f;
                mma16816(p0, p1, p2, p3,
                         a0f[0], a0f[1], a0f[2], a0f[3], b0lo, b0hi);
                accM[mt][nt][0] += p0;
                accM[mt][nt][1] += p1;
                accM[mt][nt][2] += p2;
                accM[mt][nt][3] += p3;
                // corrections, chained in TC, small -> large
                float* c = accC[mt][nt];
                mma16816(c[0], c[1], c[2], c[3],
                         a2f[0], a2f[1], a2f[2], a2f[3], b0lo, b0hi);
                mma16816(c[0], c[1], c[2], c[3],
                         a1f[0], a1f[1], a1f[2], a1f[3], b1lo, b1hi);
                mma16816(c[0], c[1], c[2], c[3],
                         a0f[0], a0f[1], a0f[2], a0f[3], b2lo, b2hi);
                mma16816(c[0], c[1], c[2], c[3],
                         a1f[0], a1f[1], a1f[2], a1f[3], b0lo, b0hi);
                mma16816(c[0], c[1], c[2], c[3],
                         a0f[0], a0f[1], a0f[2], a0f[3], b1lo, b1hi);
            }
        }
    };

    gload(klo);
    sstore(0);
    __syncthreads();
    int cur = 0;
    for (int it = 1; it < nk; it++) {
        gload(klo + it * 16);
        compute(cur);
        sstore(cur ^ 1);
        __syncthreads();
        cur ^= 1;
    }
    compute(cur);
}

// epilogue: m0/n0 of acc[mt][nt]; v* = corrections + main (RN adds)
#define EPI_LOOP(body)                                                        \
    {                                                                         \
        const int lane = threadIdx.x & 31;                                    \
        const int wm = ((threadIdx.x >> 5) >> 2) * 64;                        \
        const int wn = ((threadIdx.x >> 5) & 3) * 32;                         \
        const int g = lane >> 2, tig = lane & 3;                              \
        _Pragma("unroll") for (int mt = 0; mt < 4; mt++)                      \
            _Pragma("unroll") for (int nt = 0; nt < 4; nt++) {                \
            int m0 = bm + wm + mt * 16 + g;                                   \
            int n0 = bn + wn + nt * 8 + 2 * tig;                              \
            float v0 = accC[mt][nt][0] + accM[mt][nt][0];                     \
            float v1 = accC[mt][nt][1] + accM[mt][nt][1];                     \
            float v2 = accC[mt][nt][2] + accM[mt][nt][2];                     \
            float v3 = accC[mt][nt][3] + accM[mt][nt][3];                     \
            body                                                              \
        }                                                                     \
    }

__global__ void __launch_bounds__(256) gru_mma(const float* __restrict__ b_ih,
                                               const float* __restrict__ b_hh) {
    float accM[4][4][4] = {}, accC[4][4][4] = {};
    int bm = blockIdx.y * 128, bn = blockIdx.x * 128;
    int klo, khi;
    if (bn < 1024)      { klo = 0;    khi = KCAT; }   // rz: full K
    else if (bn < 1536) { klo = 0;    khi = 1040; }   // xn (W zero beyond 1034)
    else                { klo = 1024; khi = KCAT; }   // hn (W zero below 1034)
    mma_core(gX0, gX1, gX2, KCAT, gW0, gW1, gW2, KCAT, klo, khi, bm, bn, accM, accC);

    auto wr = [&](int m, int n, float v) {
        if (n < 1024)      g_rz[m * 1024 + n] = v + b_ih[n] + b_hh[n];
        else if (n < 1536) g_xn[m * 512 + (n - 1024)] = v + b_ih[n];
        else               g_hn[m * 512 + (n - 1536)] = v + b_hh[(n - 1536) + 1024];
    };
    EPI_LOOP({
        wr(m0, n0, v0);
        wr(m0, n0 + 1, v1);
        wr(m0 + 8, n0, v2);
        wr(m0 + 8, n0 + 1, v3);
    })
}

__global__ void __launch_bounds__(256) b1_mma(const float* __restrict__ pb1) {
    float accM[4][4][4] = {}, accC[4][4][4] = {};
    int bm = blockIdx.y * 128, bn = blockIdx.x * 128;
    mma_core(gD0, gD1, gD2, 512, gP10, gP11, gP12, 512, 0, 512, bm, bn, accM, accC);
    EPI_LOOP({
        g_h1raw[m0 * 512 + n0]           = v0 + pb1[n0];
        g_h1raw[m0 * 512 + n0 + 1]       = v1 + pb1[n0 + 1];
        g_h1raw[(m0 + 8) * 512 + n0]     = v2 + pb1[n0];
        g_h1raw[(m0 + 8) * 512 + n0 + 1] = v3 + pb1[n0 + 1];
    })
}

__global__ void __launch_bounds__(256) c_mma(const float* __restrict__ pb2) {
    float accM[4][4][4] = {}, accC[4][4][4] = {};
    int bm = blockIdx.y * 128, bn = blockIdx.x * 128;
    mma_core(gH0, gH1, gH2, 512, gP20, gP21, gP22, 512, 0, 512, bm, bn, accM, accC);
    EPI_LOOP({
        g_logits[m0 * 1024 + n0]           = v0 + pb2[n0];
        g_logits[m0 * 1024 + n0 + 1]       = v1 + pb2[n0 + 1];
        g_logits[(m0 + 8) * 1024 + n0]     = v2 + pb2[n0];
        g_logits[(m0 + 8) * 1024 + n0 + 1] = v3 + pb2[n0 + 1];
    })
}

// ---------------------------------------------------------------------------
// GRU gates: deter update; splits into gX (deter region) + gD planes
// ---------------------------------------------------------------------------
__global__ void gates_kernel(float* __restrict__ out, int t) {
    int gid = blockIdx.x * blockDim.x + threadIdx.x;
    int b = gid >> 9, d = gid & 511;
    float sr = g_rz[b * 1024 + d];
    float sz = g_rz[b * 1024 + 512 + d];
    float xn = g_xn[b * 512 + d];
    float hn = g_hn[b * 512 + d];
    float h  = g_deter[b * 512 + d];
    float r = 1.f / (1.f + expf(-sr));
    float z = 1.f / (1.f + expf(-sz));
    float n = tanhf(xn + r * hn);
    float dn = (1.f - z) * n + z * h;
    g_deter[b * 512 + d] = dn;
    out[((size_t)t * B_ + b) * OUTW + d] = dn;
    __nv_bfloat16 p0, p1, p2;
    split3(dn, p0, p1, p2);
    int xk = b * KCAT + 1034 + d;
    gX0[xk] = p0; gX1[xk] = p1; gX2[xk] = p2;
    int dk = b * 512 + d;
    gD0[dk] = p0; gD1[dk] = p1; gD2[dk] = p2;
}

// ---------------------------------------------------------------------------
// LayerNorm + SiLU -> gH planes
// ---------------------------------------------------------------------------
__global__ void ln_kernel(const float* __restrict__ pg, const float* __restrict__ pbeta) {
    __shared__ float red[256];
    int b = blockIdx.x, tid = threadIdx.x;
    const float* x = g_h1raw + b * 512;
    float v0 = x[tid], v1 = x[tid + 256];
    red[tid] = v0 + v1;
    __syncthreads();
    for (int s = 128; s > 0; s >>= 1) {
        if (tid < s) red[tid] += red[tid + s];
        __syncthreads();
    }
    float mean = red[0] * (1.f / 512.f);
    __syncthreads();
    float d0 = v0 - mean, d1 = v1 - mean;
    red[tid] = d0 * d0 + d1 * d1;
    __syncthreads();
    for (int s = 128; s > 0; s >>= 1) {
        if (tid < s) red[tid] += red[tid + s];
        __syncthreads();
    }
    float var = red[0] * (1.f / 512.f);
    float rstd = rsqrtf(var + 1e-5f);
    float y0 = d0 * rstd * pg[tid] + pbeta[tid];
    float y1 = d1 * rstd * pg[tid + 256] + pbeta[tid + 256];
    float s0 = y0 * (1.f / (1.f + expf(-y0)));
    float s1 = y1 * (1.f / (1.f + expf(-y1)));
    __nv_bfloat16 a, bb, c;
    split3(s0, a, bb, c);
    gH0[b * 512 + tid] = a; gH1[b * 512 + tid] = bb; gH2[b * 512 + tid] = c;
    split3(s1, a, bb, c);
    gH0[b * 512 + tid + 256] = a; gH1[b * 512 + tid + 256] = bb; gH2[b * 512 + tid + 256] = c;
}

// ---------------------------------------------------------------------------
// Gumbel-max sampling; writes onehot to out + gX stoch planes; stages action
// ---------------------------------------------------------------------------
__global__ void sample_kernel(const float* __restrict__ act_seq,
                              float* __restrict__ out,
                              int t, uint32_t k0, uint32_t k1) {
    int gid = blockIdx.x * blockDim.x + threadIdx.x;
    int b = gid >> 5, s = gid & 31;
    const float* lg = g_logits + b * 1024 + s * 32;
    float best = -1e30f;
    int bi = 0;
#pragma unroll 4
    for (int c = 0; c < 32; c++) {
        uint32_t idx = (uint32_t)(b * 1024 + s * 32 + c);
        uint32_t o0, o1;
        threefry2x32(k0, k1, 0u, idx, o0, o1);
        uint32_t bits = o0 ^ o1;
        float u = __uint_as_float((bits >> 9) | 0x3f800000u) - 1.0f;
        u = fmaxf(u, 1.1754943508222875e-38f);
        float g = -logf(-logf(u));
        float v = g + lg[c];
        if (v > best) { best = v; bi = c; }
    }
    const __nv_bfloat16 zero = __float2bfloat16_rn(0.f);
    const __nv_bfloat16 one  = __float2bfloat16_rn(1.f);
    int xbase = b * KCAT + s * 32;
    float* os = out + ((size_t)t * B_ + b) * OUTW + 512 + s * 32;
#pragma unroll
    for (int c = 0; c < 32; c++) {
        bool hit = (c == bi);
        os[c] = hit ? 1.0f : 0.0f;
        gX0[xbase + c] = hit ? one : zero;
        gX1[xbase + c] = zero;
        gX2[xbase + c] = zero;
    }
    if (t < H_ - 1 && s < ACT_) {
        float a = act_seq[(((size_t)(t + 1)) * B_ + b) * ACT_ + s];
        __nv_bfloat16 p0, p1, p2;
        split3(a, p0, p1, p2);
        int ak = b * KCAT + SC_ + s;
        gX0[ak] = p0; gX1[ak] = p1; gX2[ak] = p2;
    }
}

// ---------------------------------------------------------------------------
// Host launcher
// ---------------------------------------------------------------------------
extern "C" void kernel_launch(void* const* d_in, const int* in_sizes, int n_in,
                              void* d_out, int out_size) {
    const float* act    = (const float*)d_in[0];
    const float* deter0 = (const float*)d_in[1];
    const float* stoch0 = (const float*)d_in[2];
    const float* W_ih   = (const float*)d_in[3];
    const float* b_ih   = (const float*)d_in[4];
    const float* W_hh   = (const float*)d_in[5];
    const float* b_hh   = (const float*)d_in[6];
    const float* pW1    = (const float*)d_in[7];
    const float* pb1    = (const float*)d_in[8];
    const float* pg     = (const float*)d_in[9];
    const float* pbeta  = (const float*)d_in[10];
    const float* pW2    = (const float*)d_in[11];
    const float* pb2    = (const float*)d_in[12];
    float* out = (float*)d_out;

    uint32_t keys[H_][2];
    for (int t = 0; t < H_; t++) {
        uint32_t o0, o1;
        threefry2x32(0u, 42u, 0u, (uint32_t)t, o0, o1);
        keys[t][0] = o0;
        keys[t][1] = o1;
    }

    cudaFuncSetAttribute(gru_mma, cudaFuncAttributeMaxDynamicSharedMemorySize, SMEM_BYTES);
    cudaFuncSetAttribute(b1_mma,  cudaFuncAttributeMaxDynamicSharedMemorySize, SMEM_BYTES);
    cudaFuncSetAttribute(c_mma,   cudaFuncAttributeMaxDynamicSharedMemorySize, SMEM_BYTES);

    cudaStream_t st = cudaStreamPerThread;
    init_kernel<<<(B_ * KCAT + 255) / 256, 256, 0, st>>>(stoch0, act, deter0);
    wprep_kernel<<<(2048 * KCAT + 255) / 256, 256, 0, st>>>(W_ih, W_hh);
    pprep_kernel<<<((512 * 512 + 1024 * 512) + 255) / 256, 256, 0, st>>>(pW1, pW2);

    for (int t = 0; t < H_; t++) {
        gru_mma<<<dim3(16, 16), 256, SMEM_BYTES, st>>>(b_ih, b_hh);
        gates_kernel<<<(B_ * DETER_) / 256, 256, 0, st>>>(out, t);
        b1_mma<<<dim3(4, 16), 256, SMEM_BYTES, st>>>(pb1);
        ln_kernel<<<B_, 256, 0, st>>>(pg, pbeta);
        c_mma<<<dim3(8, 16), 256, SMEM_BYTES, st>>>(pb2);
        sample_kernel<<<(B_ * 32) / 128, 128, 0, st>>>(act, out, t, keys[t][0], keys[t][1]);
    }
}

// round 9
// speedup vs baseline: 2.1224x; 1.3900x over previous
#include <cuda_runtime.h>
#include <cuda_bf16.h>
#include <cstdint>

// ---------------------------------------------------------------------------
// RSSM rollout: H=16 steps, B=2048
// R7: R6 bf16x3 RZ-safe TC GEMMs +
//   - hoisted B-fragment loads (4x fewer LDS)
//   - corrections skipped where A planes 1/2 are exactly zero (stoch onehot)
//   - heavy-first 1D grid ordering for GRU wave balance
//   - b1 split-K=2 with deterministic partial-sum in ln_kernel
// ---------------------------------------------------------------------------

#define B_       2048
#define DETER_   512
#define SC_      1024
#define ACT_     10
#define H_       16
#define KCAT     1552
#define OUTW     1536

#define KPAD     24
#define PLANE_ELT (128 * KPAD)
#define SMEM_HALF (6 * PLANE_ELT)
#define SMEM_BYTES (2 * SMEM_HALF * 2)   // 73728 B

// fp32 state
__device__ float g_deter[B_ * DETER_];
__device__ float g_rz[B_ * 1024];
__device__ float g_xn[B_ * DETER_];
__device__ float g_hn[B_ * DETER_];
__device__ float g_h1p[2 * B_ * DETER_];   // b1 split-K partials
__device__ float g_logits[B_ * SC_];

// bf16x3 planes
__device__ __nv_bfloat16 gW0[2048 * KCAT], gW1[2048 * KCAT], gW2[2048 * KCAT];
__device__ __nv_bfloat16 gX0[B_ * KCAT],  gX1[B_ * KCAT],  gX2[B_ * KCAT];
__device__ __nv_bfloat16 gD0[B_ * DETER_], gD1[B_ * DETER_], gD2[B_ * DETER_];
__device__ __nv_bfloat16 gH0[B_ * DETER_], gH1[B_ * DETER_], gH2[B_ * DETER_];
__device__ __nv_bfloat16 gP10[512 * 512],  gP11[512 * 512],  gP12[512 * 512];
__device__ __nv_bfloat16 gP20[1024 * 512], gP21[1024 * 512], gP22[1024 * 512];

// ---------------------------------------------------------------------------
// Threefry-2x32 (JAX schedule) — proven bit-exact, do not touch
// ---------------------------------------------------------------------------
__host__ __device__ __forceinline__ uint32_t rotl32(uint32_t v, int d) {
    return (v << d) | (v >> (32 - d));
}
__host__ __device__ __forceinline__ void threefry2x32(uint32_t k0, uint32_t k1,
                                                      uint32_t x0, uint32_t x1,
                                                      uint32_t& o0, uint32_t& o1) {
    uint32_t ks0 = k0, ks1 = k1, ks2 = k0 ^ k1 ^ 0x1BD11BDAu;
    x0 += ks0; x1 += ks1;
    x0 += x1; x1 = rotl32(x1, 13); x1 ^= x0;
    x0 += x1; x1 = rotl32(x1, 15); x1 ^= x0;
    x0 += x1; x1 = rotl32(x1, 26); x1 ^= x0;
    x0 += x1; x1 = rotl32(x1, 6);  x1 ^= x0;
    x0 += ks1; x1 += ks2 + 1u;
    x0 += x1; x1 = rotl32(x1, 17); x1 ^= x0;
    x0 += x1; x1 = rotl32(x1, 29); x1 ^= x0;
    x0 += x1; x1 = rotl32(x1, 16); x1 ^= x0;
    x0 += x1; x1 = rotl32(x1, 24); x1 ^= x0;
    x0 += ks2; x1 += ks0 + 2u;
    x0 += x1; x1 = rotl32(x1, 13); x1 ^= x0;
    x0 += x1; x1 = rotl32(x1, 15); x1 ^= x0;
    x0 += x1; x1 = rotl32(x1, 26); x1 ^= x0;
    x0 += x1; x1 = rotl32(x1, 6);  x1 ^= x0;
    x0 += ks0; x1 += ks1 + 3u;
    x0 += x1; x1 = rotl32(x1, 17); x1 ^= x0;
    x0 += x1; x1 = rotl32(x1, 29); x1 ^= x0;
    x0 += x1; x1 = rotl32(x1, 16); x1 ^= x0;
    x0 += x1; x1 = rotl32(x1, 24); x1 ^= x0;
    x0 += ks1; x1 += ks2 + 4u;
    x0 += x1; x1 = rotl32(x1, 13); x1 ^= x0;
    x0 += x1; x1 = rotl32(x1, 15); x1 ^= x0;
    x0 += x1; x1 = rotl32(x1, 26); x1 ^= x0;
    x0 += x1; x1 = rotl32(x1, 6);  x1 ^= x0;
    x0 += ks2; x1 += ks0 + 5u;
    o0 = x0; o1 = x1;
}

// exact 3-way bf16 split
__device__ __forceinline__ void split3(float v, __nv_bfloat16& b0,
                                       __nv_bfloat16& b1, __nv_bfloat16& b2) {
    b0 = __float2bfloat16_rn(v);
    float r = v - __bfloat162float(b0);
    b1 = __float2bfloat16_rn(r);
    float r2 = r - __bfloat162float(b1);
    b2 = __float2bfloat16_rn(r2);
}

// ---------------------------------------------------------------------------
// Prep kernels (one-time)
// ---------------------------------------------------------------------------
__global__ void init_kernel(const float* __restrict__ stoch0,
                            const float* __restrict__ act_seq,
                            const float* __restrict__ deter0) {
    int gid = blockIdx.x * blockDim.x + threadIdx.x;
    if (gid >= B_ * KCAT) return;
    int b = gid / KCAT, k = gid % KCAT;
    float v = 0.f;
    if (k < SC_)             v = stoch0[b * SC_ + k];
    else if (k < SC_ + ACT_) v = act_seq[b * ACT_ + (k - SC_)];
    else if (k < 1546)       v = deter0[b * DETER_ + (k - SC_ - ACT_)];
    split3(v, gX0[gid], gX1[gid], gX2[gid]);
    if (k < DETER_) {
        float d = deter0[b * DETER_ + k];
        g_deter[b * DETER_ + k] = d;
        split3(d, gD0[b * DETER_ + k], gD1[b * DETER_ + k], gD2[b * DETER_ + k]);
    }
}

__global__ void wprep_kernel(const float* __restrict__ W_ih,
                             const float* __restrict__ W_hh) {
    int gid = blockIdx.x * blockDim.x + threadIdx.x;
    if (gid >= 2048 * KCAT) return;
    int r = gid / KCAT, k = gid % KCAT;
    float v = 0.f;
    if (r < 1024) {
        if (k < 1034)       v = W_ih[r * 1034 + k];
        else if (k < 1546)  v = W_hh[r * 512 + (k - 1034)];
    } else if (r < 1536) {
        if (k < 1034)       v = W_ih[r * 1034 + k];
    } else {
        if (k >= 1034 && k < 1546) v = W_hh[(r - 512) * 512 + (k - 1034)];
    }
    split3(v, gW0[gid], gW1[gid], gW2[gid]);
}

__global__ void pprep_kernel(const float* __restrict__ pW1,
                             const float* __restrict__ pW2) {
    int gid = blockIdx.x * blockDim.x + threadIdx.x;
    if (gid < 512 * 512) {
        split3(pW1[gid], gP10[gid], gP11[gid], gP12[gid]);
    } else if (gid < 512 * 512 + 1024 * 512) {
        int i = gid - 512 * 512;
        split3(pW2[i], gP20[i], gP21[i], gP22[i]);
    }
}

// ---------------------------------------------------------------------------
// MMA primitives
// ---------------------------------------------------------------------------
__device__ __forceinline__ void mma16816(float& c0, float& c1, float& c2, float& c3,
                                         uint32_t a0, uint32_t a1, uint32_t a2, uint32_t a3,
                                         uint32_t b0, uint32_t b1) {
    asm volatile(
        "mma.sync.aligned.m16n8k16.row.col.f32.bf16.bf16.f32 "
        "{%0,%1,%2,%3}, {%4,%5,%6,%7}, {%8,%9}, {%0,%1,%2,%3};"
        : "+f"(c0), "+f"(c1), "+f"(c2), "+f"(c3)
        : "r"(a0), "r"(a1), "r"(a2), "r"(a3), "r"(b0), "r"(b1));
}

__device__ __forceinline__ void ldm_x4(uint32_t& r0, uint32_t& r1,
                                       uint32_t& r2, uint32_t& r3, uint32_t addr) {
    asm volatile("ldmatrix.sync.aligned.m8n8.x4.shared.b16 {%0,%1,%2,%3}, [%4];"
                 : "=r"(r0), "=r"(r1), "=r"(r2), "=r"(r3) : "r"(addr));
}

// ---------------------------------------------------------------------------
// bf16x3 MMA core, RZ-safe. corr_klo: k below which A planes 1/2 are exactly
// zero (their products are skipped entirely — math unchanged).
// ---------------------------------------------------------------------------
__device__ __forceinline__ void mma_core(
    const __nv_bfloat16* __restrict__ A0, const __nv_bfloat16* __restrict__ A1,
    const __nv_bfloat16* __restrict__ A2, int lda,
    const __nv_bfloat16* __restrict__ B0, const __nv_bfloat16* __restrict__ B1,
    const __nv_bfloat16* __restrict__ B2, int ldb,
    int klo, int khi, int corr_klo, int bm, int bn,
    float (&accM)[4][4][4], float (&accC)[4][4][4]) {
    extern __shared__ __nv_bfloat16 sm[];
    const int tid = threadIdx.x;
    const int lane = tid & 31;
    const int wm = ((tid >> 5) >> 2) * 64;
    const int wn = ((tid >> 5) & 3) * 32;
    const int g = lane >> 2, tig = lane & 3;
    const int lrow = tid >> 1, lhalf = tid & 1;

    const __nv_bfloat16* Ap[3] = {
        A0 + (size_t)(bm + lrow) * lda + lhalf * 8,
        A1 + (size_t)(bm + lrow) * lda + lhalf * 8,
        A2 + (size_t)(bm + lrow) * lda + lhalf * 8};
    const __nv_bfloat16* Bp[3] = {
        B0 + (size_t)(bn + lrow) * ldb + lhalf * 8,
        B1 + (size_t)(bn + lrow) * ldb + lhalf * 8,
        B2 + (size_t)(bn + lrow) * ldb + lhalf * 8};

    const uint32_t smbase = (uint32_t)__cvta_generic_to_shared(sm);
    const int nk = (khi - klo) >> 4;
    const int st_off = lrow * KPAD + lhalf * 8;

    uint4 pa[3], pb[3];
    bool gf = false;
    bool corrbuf[2] = {false, false};

    auto gload = [&](int k0) {
        gf = (k0 >= corr_klo);
        pa[0] = *(const uint4*)(Ap[0] + k0);
#pragma unroll
        for (int p = 0; p < 3; p++) pb[p] = *(const uint4*)(Bp[p] + k0);
        if (gf) {
            pa[1] = *(const uint4*)(Ap[1] + k0);
            pa[2] = *(const uint4*)(Ap[2] + k0);
        }
    };
    auto sstore = [&](int buf) {
        __nv_bfloat16* base = sm + buf * SMEM_HALF;
        *(uint4*)(base + 0 * PLANE_ELT + st_off) = pa[0];
#pragma unroll
        for (int p = 0; p < 3; p++)
            *(uint4*)(base + (3 + p) * PLANE_ELT + st_off) = pb[p];
        if (gf) {
            *(uint4*)(base + 1 * PLANE_ELT + st_off) = pa[1];
            *(uint4*)(base + 2 * PLANE_ELT + st_off) = pa[2];
        }
        corrbuf[buf] = gf;
    };
    auto compute = [&](int buf) {
        const bool corr = corrbuf[buf];
        const uint32_t abase = smbase + (uint32_t)(buf * SMEM_HALF) * 2;
        const __nv_bfloat16* sbb = sm + buf * SMEM_HALF + 3 * PLANE_ELT;
        // hoisted B fragments: all planes, all nt
        uint32_t bf[3][4][2];
#pragma unroll
        for (int nt = 0; nt < 4; nt++) {
            const __nv_bfloat16* bq = sbb + (wn + nt * 8 + g) * KPAD + 2 * tig;
#pragma unroll
            for (int p = 0; p < 3; p++) {
                bf[p][nt][0] = *(const uint32_t*)(bq + p * PLANE_ELT);
                bf[p][nt][1] = *(const uint32_t*)(bq + p * PLANE_ELT + 8);
            }
        }
#pragma unroll
        for (int mt = 0; mt < 4; mt++) {
            uint32_t a0f[4], a1f[4], a2f[4];
            uint32_t arow = (uint32_t)((wm + mt * 16 + (lane & 15)) * KPAD * 2) +
                            (uint32_t)((lane >> 4) * 16);
            ldm_x4(a0f[0], a0f[1], a0f[2], a0f[3], abase + 0 * PLANE_ELT * 2 + arow);
            if (corr) {
                ldm_x4(a1f[0], a1f[1], a1f[2], a1f[3], abase + 1 * PLANE_ELT * 2 + arow);
                ldm_x4(a2f[0], a2f[1], a2f[2], a2f[3], abase + 2 * PLANE_ELT * 2 + arow);
            }
#pragma unroll
            for (int nt = 0; nt < 4; nt++) {
                // main product: fresh C=0, RN FADD flush
                float p0 = 0.f, p1 = 0.f, p2 = 0.f, p3 = 0.f;
                mma16816(p0, p1, p2, p3,
                         a0f[0], a0f[1], a0f[2], a0f[3],
                         bf[0][nt][0], bf[0][nt][1]);
                accM[mt][nt][0] += p0;
                accM[mt][nt][1] += p1;
                accM[mt][nt][2] += p2;
                accM[mt][nt][3] += p3;
                // corrections, chained in TC, small -> large
                float* c = accC[mt][nt];
                if (corr) {
                    mma16816(c[0], c[1], c[2], c[3],
                             a2f[0], a2f[1], a2f[2], a2f[3],
                             bf[0][nt][0], bf[0][nt][1]);
                    mma16816(c[0], c[1], c[2], c[3],
                             a1f[0], a1f[1], a1f[2], a1f[3],
                             bf[1][nt][0], bf[1][nt][1]);
                }
                mma16816(c[0], c[1], c[2], c[3],
                         a0f[0], a0f[1], a0f[2], a0f[3],
                         bf[2][nt][0], bf[2][nt][1]);
                if (corr) {
                    mma16816(c[0], c[1], c[2], c[3],
                             a1f[0], a1f[1], a1f[2], a1f[3],
                             bf[0][nt][0], bf[0][nt][1]);
                }
                mma16816(c[0], c[1], c[2], c[3],
                         a0f[0], a0f[1], a0f[2], a0f[3],
                         bf[1][nt][0], bf[1][nt][1]);
            }
        }
    };

    gload(klo);
    sstore(0);
    __syncthreads();
    int cur = 0;
    for (int it = 1; it < nk; it++) {
        gload(klo + it * 16);
        compute(cur);
        sstore(cur ^ 1);
        __syncthreads();
        cur ^= 1;
    }
    compute(cur);
}

#define EPI_LOOP(body)                                                        \
    {                                                                         \
        const int lane = threadIdx.x & 31;                                    \
        const int wm = ((threadIdx.x >> 5) >> 2) * 64;                        \
        const int wn = ((threadIdx.x >> 5) & 3) * 32;                         \
        const int g = lane >> 2, tig = lane & 3;                              \
        _Pragma("unroll") for (int mt = 0; mt < 4; mt++)                      \
            _Pragma("unroll") for (int nt = 0; nt < 4; nt++) {                \
            int m0 = bm + wm + mt * 16 + g;                                   \
            int n0 = bn + wn + nt * 8 + 2 * tig;                              \
            float v0 = accC[mt][nt][0] + accM[mt][nt][0];                     \
            float v1 = accC[mt][nt][1] + accM[mt][nt][1];                     \
            float v2 = accC[mt][nt][2] + accM[mt][nt][2];                     \
            float v3 = accC[mt][nt][3] + accM[mt][nt][3];                     \
            body                                                              \
        }                                                                     \
    }

// ---------------------------------------------------------------------------
// GRU GEMM: 1D grid, heavy-first tile order. corr_klo=1024 (stoch onehot).
// ---------------------------------------------------------------------------
__global__ void __launch_bounds__(256) gru_mma(const float* __restrict__ b_ih,
                                               const float* __restrict__ b_hh) {
    float accM[4][4][4] = {}, accC[4][4][4] = {};
    int bid = blockIdx.x;
    int bmT, bnT;
    if (bid < 128)      { bnT = bid & 7;             bmT = bid >> 3; }       // rz (97 slabs)
    else if (bid < 192) { int r = bid - 128; bnT = 8 + (r & 3);  bmT = r >> 2; }  // xn (65)
    else                { int r = bid - 192; bnT = 12 + (r & 3); bmT = r >> 2; }  // hn (33)
    int bm = bmT * 128, bn = bnT * 128;
    int klo, khi;
    if (bnT < 8)       { klo = 0;    khi = KCAT; }
    else if (bnT < 12) { klo = 0;    khi = 1040; }
    else               { klo = 1024; khi = KCAT; }
    mma_core(gX0, gX1, gX2, KCAT, gW0, gW1, gW2, KCAT,
             klo, khi, /*corr_klo=*/1024, bm, bn, accM, accC);

    auto wr = [&](int m, int n, float v) {
        if (n < 1024)      g_rz[m * 1024 + n] = v + b_ih[n] + b_hh[n];
        else if (n < 1536) g_xn[m * 512 + (n - 1024)] = v + b_ih[n];
        else               g_hn[m * 512 + (n - 1536)] = v + b_hh[(n - 1536) + 1024];
    };
    EPI_LOOP({
        wr(m0, n0, v0);
        wr(m0, n0 + 1, v1);
        wr(m0 + 8, n0, v2);
        wr(m0 + 8, n0 + 1, v3);
    })
}

// b1: split-K=2, partials (no bias) -> g_h1p[z]
__global__ void __launch_bounds__(256) b1_mma() {
    float accM[4][4][4] = {}, accC[4][4][4] = {};
    int bm = blockIdx.y * 128, bn = blockIdx.x * 128;
    int z = blockIdx.z;
    mma_core(gD0, gD1, gD2, 512, gP10, gP11, gP12, 512,
             z * 256, (z + 1) * 256, /*corr_klo=*/0, bm, bn, accM, accC);
    float* dst = g_h1p + (size_t)z * B_ * 512;
    EPI_LOOP({
        dst[m0 * 512 + n0]           = v0;
        dst[m0 * 512 + n0 + 1]       = v1;
        dst[(m0 + 8) * 512 + n0]     = v2;
        dst[(m0 + 8) * 512 + n0 + 1] = v3;
    })
}

__global__ void __launch_bounds__(256) c_mma(const float* __restrict__ pb2) {
    float accM[4][4][4] = {}, accC[4][4][4] = {};
    int bm = blockIdx.y * 128, bn = blockIdx.x * 128;
    mma_core(gH0, gH1, gH2, 512, gP20, gP21, gP22, 512,
             0, 512, /*corr_klo=*/0, bm, bn, accM, accC);
    EPI_LOOP({
        g_logits[m0 * 1024 + n0]           = v0 + pb2[n0];
        g_logits[m0 * 1024 + n0 + 1]       = v1 + pb2[n0 + 1];
        g_logits[(m0 + 8) * 1024 + n0]     = v2 + pb2[n0];
        g_logits[(m0 + 8) * 1024 + n0 + 1] = v3 + pb2[n0 + 1];
    })
}

// ---------------------------------------------------------------------------
// GRU gates
// ---------------------------------------------------------------------------
__global__ void gates_kernel(float* __restrict__ out, int t) {
    int gid = blockIdx.x * blockDim.x + threadIdx.x;
    int b = gid >> 9, d = gid & 511;
    float sr = g_rz[b * 1024 + d];
    float sz = g_rz[b * 1024 + 512 + d];
    float xn = g_xn[b * 512 + d];
    float hn = g_hn[b * 512 + d];
    float h  = g_deter[b * 512 + d];
    float r = 1.f / (1.f + expf(-sr));
    float z = 1.f / (1.f + expf(-sz));
    float n = tanhf(xn + r * hn);
    float dn = (1.f - z) * n + z * h;
    g_deter[b * 512 + d] = dn;
    out[((size_t)t * B_ + b) * OUTW + d] = dn;
    __nv_bfloat16 p0, p1, p2;
    split3(dn, p0, p1, p2);
    int xk = b * KCAT + 1034 + d;
    gX0[xk] = p0; gX1[xk] = p1; gX2[xk] = p2;
    int dk = b * 512 + d;
    gD0[dk] = p0; gD1[dk] = p1; gD2[dk] = p2;
}

// ---------------------------------------------------------------------------
// LayerNorm + SiLU; sums split-K partials + bias (fixed RN order)
// ---------------------------------------------------------------------------
__global__ void ln_kernel(const float* __restrict__ pg,
                          const float* __restrict__ pbeta,
                          const float* __restrict__ pb1) {
    __shared__ float red[256];
    int b = blockIdx.x, tid = threadIdx.x;
    const float* x0 = g_h1p + b * 512;
    const float* x1 = g_h1p + (size_t)B_ * 512 + b * 512;
    float v0 = (x0[tid] + x1[tid]) + pb1[tid];
    float v1 = (x0[tid + 256] + x1[tid + 256]) + pb1[tid + 256];
    red[tid] = v0 + v1;
    __syncthreads();
    for (int s = 128; s > 0; s >>= 1) {
        if (tid < s) red[tid] += red[tid + s];
        __syncthreads();
    }
    float mean = red[0] * (1.f / 512.f);
    __syncthreads();
    float d0 = v0 - mean, d1 = v1 - mean;
    red[tid] = d0 * d0 + d1 * d1;
    __syncthreads();
    for (int s = 128; s > 0; s >>= 1) {
        if (tid < s) red[tid] += red[tid + s];
        __syncthreads();
    }
    float var = red[0] * (1.f / 512.f);
    float rstd = rsqrtf(var + 1e-5f);
    float y0 = d0 * rstd * pg[tid] + pbeta[tid];
    float y1 = d1 * rstd * pg[tid + 256] + pbeta[tid + 256];
    float s0 = y0 * (1.f / (1.f + expf(-y0)));
    float s1 = y1 * (1.f / (1.f + expf(-y1)));
    __nv_bfloat16 a, bb, c;
    split3(s0, a, bb, c);
    gH0[b * 512 + tid] = a; gH1[b * 512 + tid] = bb; gH2[b * 512 + tid] = c;
    split3(s1, a, bb, c);
    gH0[b * 512 + tid + 256] = a; gH1[b * 512 + tid + 256] = bb; gH2[b * 512 + tid + 256] = c;
}

// ---------------------------------------------------------------------------
// Gumbel-max sampling
// ---------------------------------------------------------------------------
__global__ void sample_kernel(const float* __restrict__ act_seq,
                              float* __restrict__ out,
                              int t, uint32_t k0, uint32_t k1) {
    int gid = blockIdx.x * blockDim.x + threadIdx.x;
    int b = gid >> 5, s = gid & 31;
    const float* lg = g_logits + b * 1024 + s * 32;
    float best = -1e30f;
    int bi = 0;
#pragma unroll 4
    for (int c = 0; c < 32; c++) {
        uint32_t idx = (uint32_t)(b * 1024 + s * 32 + c);
        uint32_t o0, o1;
        threefry2x32(k0, k1, 0u, idx, o0, o1);
        uint32_t bits = o0 ^ o1;
        float u = __uint_as_float((bits >> 9) | 0x3f800000u) - 1.0f;
        u = fmaxf(u, 1.1754943508222875e-38f);
        float g = -logf(-logf(u));
        float v = g + lg[c];
        if (v > best) { best = v; bi = c; }
    }
    const __nv_bfloat16 zero = __float2bfloat16_rn(0.f);
    const __nv_bfloat16 one  = __float2bfloat16_rn(1.f);
    int xbase = b * KCAT + s * 32;
    float* os = out + ((size_t)t * B_ + b) * OUTW + 512 + s * 32;
#pragma unroll
    for (int c = 0; c < 32; c++) {
        bool hit = (c == bi);
        os[c] = hit ? 1.0f : 0.0f;
        gX0[xbase + c] = hit ? one : zero;
        gX1[xbase + c] = zero;
        gX2[xbase + c] = zero;
    }
    if (t < H_ - 1 && s < ACT_) {
        float a = act_seq[(((size_t)(t + 1)) * B_ + b) * ACT_ + s];
        __nv_bfloat16 p0, p1, p2;
        split3(a, p0, p1, p2);
        int ak = b * KCAT + SC_ + s;
        gX0[ak] = p0; gX1[ak] = p1; gX2[ak] = p2;
    }
}

// ---------------------------------------------------------------------------
// Host launcher
// ---------------------------------------------------------------------------
extern "C" void kernel_launch(void* const* d_in, const int* in_sizes, int n_in,
                              void* d_out, int out_size) {
    const float* act    = (const float*)d_in[0];
    const float* deter0 = (const float*)d_in[1];
    const float* stoch0 = (const float*)d_in[2];
    const float* W_ih   = (const float*)d_in[3];
    const float* b_ih   = (const float*)d_in[4];
    const float* W_hh   = (const float*)d_in[5];
    const float* b_hh   = (const float*)d_in[6];
    const float* pW1    = (const float*)d_in[7];
    const float* pb1    = (const float*)d_in[8];
    const float* pg     = (const float*)d_in[9];
    const float* pbeta  = (const float*)d_in[10];
    const float* pW2    = (const float*)d_in[11];
    const float* pb2    = (const float*)d_in[12];
    float* out = (float*)d_out;

    uint32_t keys[H_][2];
    for (int t = 0; t < H_; t++) {
        uint32_t o0, o1;
        threefry2x32(0u, 42u, 0u, (uint32_t)t, o0, o1);
        keys[t][0] = o0;
        keys[t][1] = o1;
    }

    cudaFuncSetAttribute(gru_mma, cudaFuncAttributeMaxDynamicSharedMemorySize, SMEM_BYTES);
    cudaFuncSetAttribute(b1_mma,  cudaFuncAttributeMaxDynamicSharedMemorySize, SMEM_BYTES);
    cudaFuncSetAttribute(c_mma,   cudaFuncAttributeMaxDynamicSharedMemorySize, SMEM_BYTES);

    cudaStream_t st = cudaStreamPerThread;
    init_kernel<<<(B_ * KCAT + 255) / 256, 256, 0, st>>>(stoch0, act, deter0);
    wprep_kernel<<<(2048 * KCAT + 255) / 256, 256, 0, st>>>(W_ih, W_hh);
    pprep_kernel<<<((512 * 512 + 1024 * 512) + 255) / 256, 256, 0, st>>>(pW1, pW2);

    for (int t = 0; t < H_; t++) {
        gru_mma<<<256, 256, SMEM_BYTES, st>>>(b_ih, b_hh);
        gates_kernel<<<(B_ * DETER_) / 256, 256, 0, st>>>(out, t);
        b1_mma<<<dim3(4, 16, 2), 256, SMEM_BYTES, st>>>();
        ln_kernel<<<B_, 256, 0, st>>>(pg, pbeta, pb1);
        c_mma<<<dim3(8, 16), 256, SMEM_BYTES, st>>>(pb2);
        sample_kernel<<<(B_ * 32) / 128, 128, 0, st>>>(act, out, t, keys[t][0], keys[t][1]);
    }
}